// round 1
// baseline (speedup 1.0000x reference)
#include <cuda_runtime.h>
#include <math.h>

#define BB 4
#define CC 256
#define HH 64
#define WW 64
#define HW 4096
#define K9 9
#define KK 2304   // 256*9
#define NG 32
#define CPG 8     // channels per group

// ---------------- static scratch (no allocations allowed) ----------------
__device__ float g_cols[(size_t)BB * KK * HW];   // 151 MB, reused 4x
__device__ float g_t[BB * CC * HW];              // GN(conv1) output
__device__ float g_raw[BB * CC * HW];            // pre-GN conv outputs
__device__ float g_wT1[KK * 256];                // conv1 weights, [kk][oc]
__device__ float g_wT2[KK * 128];                // conv2 (18 out, padded to 128)
__device__ float g_wTc[KK * 256];                // cls deform weights
__device__ float g_wTr[KK * 256];                // reg deform weights
__device__ float g_mu[BB * NG];
__device__ float g_rstd[BB * NG];

// ---------------- weight transpose: w[O][256][9] -> wT[(tap*256+ci)][o] ----
__global__ void transpose_w(const float* __restrict__ w, float* __restrict__ wT,
                            int O, int ldo) {
    int i = blockIdx.x * 256 + threadIdx.x;
    int total = KK * ldo;
    if (i >= total) return;
    int o = i % ldo;
    int kk = i / ldo;
    int ci = kk % CC;
    int tap = kk / CC;
    wT[i] = (o < O) ? w[(o * CC + ci) * K9 + tap] : 0.f;
}

// ---------------- im2col for 3x3, pad 1: cols[b][tap*256+ci][m] ------------
__global__ void im2col9(const float* __restrict__ in, float* __restrict__ cols) {
    int i = blockIdx.x * 256 + threadIdx.x;     // exact grid: BB*KK*HW threads
    int m = i & (HW - 1);
    int r = i >> 12;
    int kk = r % KK;
    int b = r / KK;
    int ci = kk % CC;
    int tap = kk / CC;
    int y = (m >> 6) + (tap / 3) - 1;
    int x = (m & 63) + (tap % 3) - 1;
    float v = 0.f;
    if ((unsigned)y < 64u && (unsigned)x < 64u)
        v = in[((b * CC + ci) * HH + y) * WW + x];
    cols[i] = v;
}

// ---------------- deformable sampling: cols[b][k*256+c][m] ----------------
// sample pos: py = pts_y + y ; px = ((pts_x - bx) + x) + bx  (matches ref fp order)
__global__ void deform_cols(const float* __restrict__ img,
                            const float* __restrict__ pts,
                            float* __restrict__ cols) {
    int m = blockIdx.x * 256 + threadIdx.x;     // 0..4095
    int k = blockIdx.y;
    int b = blockIdx.z;
    int y = m >> 6, x = m & 63;
    float pty = pts[(b * 18 + 2 * k) * HW + m];
    float ptx = pts[(b * 18 + 2 * k + 1) * HW + m];
    float bx = (float)(k - 4);
    float py = pty + (float)y;
    float px = ((ptx - bx) + (float)x) + bx;
    float y0f = floorf(py), x0f = floorf(px);
    int y0 = (int)y0f, x0 = (int)x0f;
    float wy = py - y0f, wx = px - x0f;
    float w00 = (1.f - wy) * (1.f - wx);
    float w01 = (1.f - wy) * wx;
    float w10 = wy * (1.f - wx);
    float w11 = wy * wx;
    bool vy0 = (y0 >= 0) && (y0 <= 63);
    bool vy1 = (y0 + 1 >= 0) && (y0 + 1 <= 63);
    bool vx0 = (x0 >= 0) && (x0 <= 63);
    bool vx1 = (x0 + 1 >= 0) && (x0 + 1 <= 63);
    w00 = (vy0 && vx0) ? w00 : 0.f;
    w01 = (vy0 && vx1) ? w01 : 0.f;
    w10 = (vy1 && vx0) ? w10 : 0.f;
    w11 = (vy1 && vx1) ? w11 : 0.f;
    int y0c = min(max(y0, 0), 63), y1c = min(max(y0 + 1, 0), 63);
    int x0c = min(max(x0, 0), 63), x1c = min(max(x0 + 1, 0), 63);
    int i00 = y0c * 64 + x0c, i01 = y0c * 64 + x1c;
    int i10 = y1c * 64 + x0c, i11 = y1c * 64 + x1c;
    const float* ib = img + (size_t)b * CC * HW;
    float* cb = cols + ((size_t)b * KK + (size_t)k * CC) * HW + m;
#pragma unroll 4
    for (int c = 0; c < CC; c++) {
        const float* ic = ib + (size_t)c * HW;
        float v = w00 * __ldg(ic + i00) + w01 * __ldg(ic + i01)
                + w10 * __ldg(ic + i10) + w11 * __ldg(ic + i11);
        cb[(size_t)c * HW] = v;
    }
}

// ---------------- GroupNorm stats: one block per (b,g) --------------------
__global__ void gn_stats(const float* __restrict__ raw) {
    int bg = blockIdx.x;                         // b*32+g; group chans contiguous
    const float* p = raw + (size_t)bg * CPG * HW;
    float s = 0.f, ss = 0.f;
    for (int i = threadIdx.x; i < CPG * HW; i += 256) {
        float v = p[i];
        s += v; ss += v * v;
    }
    __shared__ float sh[512];
    sh[threadIdx.x] = s;
    sh[256 + threadIdx.x] = ss;
    __syncthreads();
    for (int o = 128; o > 0; o >>= 1) {
        if (threadIdx.x < o) {
            sh[threadIdx.x] += sh[threadIdx.x + o];
            sh[256 + threadIdx.x] += sh[256 + threadIdx.x + o];
        }
        __syncthreads();
    }
    if (threadIdx.x == 0) {
        const float inv_n = 1.f / (float)(CPG * HW);
        float mean = sh[0] * inv_n;
        float var = sh[256] * inv_n - mean * mean;
        g_mu[bg] = mean;
        g_rstd[bg] = rsqrtf(var + 1e-5f);
    }
}

// ---------------- normalize + affine + ReLU -------------------------------
__global__ void gn_apply(const float* __restrict__ raw,
                         const float* __restrict__ gamma,
                         const float* __restrict__ beta,
                         float* __restrict__ out) {
    int i = blockIdx.x * 256 + threadIdx.x;     // exact: BB*CC*HW threads
    int c = (i >> 12) & 255;
    int bg = i >> 15;                            // /(8*4096)
    float v = (raw[i] - g_mu[bg]) * g_rstd[bg] * gamma[c] + beta[c];
    out[i] = fmaxf(v, 0.f);
}

// ---------------- SGEMM: C[b][n][m] = sum_kk A[b][kk][m] * Bw[kk][n] -------
// BM=BN=128, BK=8, 256 threads, 8x8 per-thread tile.
__global__ void __launch_bounds__(256, 2)
sgemm128(const float* __restrict__ A,      // [B][KK][HW]
         const float* __restrict__ Bw,     // [KK][ldb]
         float* __restrict__ Cout,
         const float* __restrict__ bias,   // [Nreal] or nullptr
         int Nreal, int ldb, long cBatch) {
    __shared__ float As[8][128];
    __shared__ float Bs[8][128];
    int bm = blockIdx.x * 128, bn = blockIdx.y * 128, b = blockIdx.z;
    const float* Ab = A + (size_t)b * KK * HW + bm;
    const float* Bb = Bw + bn;
    int t = threadIdx.x;
    int lr = t >> 5, lc = (t & 31) * 4;
    int tx = t & 15, ty = t >> 4;

    float acc[8][8];
#pragma unroll
    for (int j = 0; j < 8; j++)
#pragma unroll
        for (int i = 0; i < 8; i++) acc[j][i] = 0.f;

    for (int k0 = 0; k0 < KK; k0 += 8) {
        float4 a4 = *(const float4*)(Ab + (size_t)(k0 + lr) * HW + lc);
        float4 b4 = *(const float4*)(Bb + (size_t)(k0 + lr) * ldb + lc);
        *(float4*)&As[lr][lc] = a4;
        *(float4*)&Bs[lr][lc] = b4;
        __syncthreads();
#pragma unroll
        for (int kk = 0; kk < 8; kk++) {
            float a[8], w[8];
            *(float4*)&a[0] = *(const float4*)&As[kk][tx * 8];
            *(float4*)&a[4] = *(const float4*)&As[kk][tx * 8 + 4];
            *(float4*)&w[0] = *(const float4*)&Bs[kk][ty * 8];
            *(float4*)&w[4] = *(const float4*)&Bs[kk][ty * 8 + 4];
#pragma unroll
            for (int j = 0; j < 8; j++)
#pragma unroll
                for (int i = 0; i < 8; i++)
                    acc[j][i] += w[j] * a[i];
        }
        __syncthreads();
    }

#pragma unroll
    for (int j = 0; j < 8; j++) {
        int n = bn + ty * 8 + j;
        if (n < Nreal) {
            float bv = bias ? bias[n] : 0.f;
            float* cp = Cout + (size_t)b * cBatch + (size_t)n * HW + bm + tx * 8;
#pragma unroll
            for (int i = 0; i < 8; i++) cp[i] = acc[j][i] + bv;
        }
    }
}

// ---------------- launch ---------------------------------------------------
extern "C" void kernel_launch(void* const* d_in, const int* in_sizes, int n_in,
                              void* d_out, int out_size) {
    const float* cls_feat = (const float*)d_in[0];
    const float* reg_feat = (const float*)d_in[1];
    const float* offc_w   = (const float*)d_in[2];
    const float* offc_b   = (const float*)d_in[3];
    const float* offc_g   = (const float*)d_in[4];
    const float* offc_bt  = (const float*)d_in[5];
    const float* offo_w   = (const float*)d_in[6];
    const float* offo_b   = (const float*)d_in[7];
    const float* clsdc_w  = (const float*)d_in[8];
    const float* cls_g    = (const float*)d_in[9];
    const float* cls_bt   = (const float*)d_in[10];
    const float* regdc_w  = (const float*)d_in[11];
    const float* reg_g    = (const float*)d_in[12];
    const float* reg_bt   = (const float*)d_in[13];

    float* out = (float*)d_out;
    float* pts = out;                         // [4][18][4096]
    float* cls_out = out + (size_t)BB * 18 * HW;
    float* reg_out = cls_out + (size_t)BB * CC * HW;

    float *cols, *t, *raw, *wT1, *wT2, *wTc, *wTr;
    cudaGetSymbolAddress((void**)&cols, g_cols);
    cudaGetSymbolAddress((void**)&t, g_t);
    cudaGetSymbolAddress((void**)&raw, g_raw);
    cudaGetSymbolAddress((void**)&wT1, g_wT1);
    cudaGetSymbolAddress((void**)&wT2, g_wT2);
    cudaGetSymbolAddress((void**)&wTc, g_wTc);
    cudaGetSymbolAddress((void**)&wTr, g_wTr);

    // weight transposes (tiny)
    transpose_w<<<(KK * 256 + 255) / 256, 256>>>(offc_w, wT1, 256, 256);
    transpose_w<<<(KK * 128 + 255) / 256, 256>>>(offo_w, wT2, 18, 128);
    transpose_w<<<(KK * 256 + 255) / 256, 256>>>(clsdc_w, wTc, 256, 256);
    transpose_w<<<(KK * 256 + 255) / 256, 256>>>(regdc_w, wTr, 256, 256);

    const int colsBlocks = (BB * KK * HW) / 256;
    const dim3 gBig(32, 2, 4);   // N=256
    const dim3 gPts(32, 1, 4);   // N=18 (padded 128)
    const dim3 gDef(16, 9, 4);

    // ---- offset branch: conv1 -> GN -> ReLU -> conv2 -> pts ----
    im2col9<<<colsBlocks, 256>>>(reg_feat, cols);
    sgemm128<<<gBig, 256>>>(cols, wT1, raw, offc_b, 256, 256, (long)CC * HW);
    gn_stats<<<BB * NG, 256>>>(raw);
    gn_apply<<<(BB * CC * HW) / 256, 256>>>(raw, offc_g, offc_bt, t);
    im2col9<<<colsBlocks, 256>>>(t, cols);
    sgemm128<<<gPts, 256>>>(cols, wT2, pts, offo_b, 18, 128, 18L * HW);

    // ---- cls branch: deform conv -> GN -> ReLU ----
    deform_cols<<<gDef, 256>>>(cls_feat, pts, cols);
    sgemm128<<<gBig, 256>>>(cols, wTc, raw, nullptr, 256, 256, (long)CC * HW);
    gn_stats<<<BB * NG, 256>>>(raw);
    gn_apply<<<(BB * CC * HW) / 256, 256>>>(raw, cls_g, cls_bt, cls_out);

    // ---- reg branch: deform conv -> GN -> ReLU ----
    deform_cols<<<gDef, 256>>>(reg_feat, pts, cols);
    sgemm128<<<gBig, 256>>>(cols, wTr, raw, nullptr, 256, 256, (long)CC * HW);
    gn_stats<<<BB * NG, 256>>>(raw);
    gn_apply<<<(BB * CC * HW) / 256, 256>>>(raw, reg_g, reg_bt, reg_out);
}

// round 2
// speedup vs baseline: 2.1525x; 2.1525x over previous
#include <cuda_runtime.h>
#include <math.h>
#include <stdint.h>

#define BB 4
#define CC 256
#define HH 64
#define WW 64
#define HW 4096
#define K9 9
#define KK 2304   // 256*9
#define NG 32
#define CPG 8     // channels per group

// ---------------- static scratch (no allocations allowed) ----------------
__device__ float g_cols[(size_t)BB * KK * HW];   // 151 MB, reused 4x
__device__ float g_t[BB * CC * HW];              // GN(conv1) output
__device__ float g_raw[BB * CC * HW];            // pre-GN conv outputs
__device__ float g_wT1[KK * 256];                // conv1 weights, [kk][oc]
__device__ float g_wT2[KK * 128];                // conv2 (18 out, padded to 128)
__device__ float g_wTc[KK * 256];                // cls deform weights
__device__ float g_wTr[KK * 256];                // reg deform weights
__device__ float g_mu[BB * NG];
__device__ float g_rstd[BB * NG];

// ---------------- weight transpose: w[O][256][9] -> wT[(tap*256+ci)][o] ----
__global__ void transpose_w(const float* __restrict__ w, float* __restrict__ wT,
                            int O, int ldo) {
    int i = blockIdx.x * 256 + threadIdx.x;
    int total = KK * ldo;
    if (i >= total) return;
    int o = i % ldo;
    int kk = i / ldo;
    int ci = kk % CC;
    int tap = kk / CC;
    wT[i] = (o < O) ? w[(o * CC + ci) * K9 + tap] : 0.f;
}

// ---------------- im2col for 3x3, pad 1: cols[b][tap*256+ci][m] ------------
__global__ void im2col9(const float* __restrict__ in, float* __restrict__ cols) {
    int i = blockIdx.x * 256 + threadIdx.x;     // exact grid: BB*KK*HW threads
    int m = i & (HW - 1);
    int r = i >> 12;
    int kk = r % KK;
    int b = r / KK;
    int ci = kk % CC;
    int tap = kk / CC;
    int y = (m >> 6) + (tap / 3) - 1;
    int x = (m & 63) + (tap % 3) - 1;
    float v = 0.f;
    if ((unsigned)y < 64u && (unsigned)x < 64u)
        v = in[((b * CC + ci) * HH + y) * WW + x];
    cols[i] = v;
}

// ---------------- deformable sampling: cols[b][k*256+c][m] ----------------
__global__ void deform_cols(const float* __restrict__ img,
                            const float* __restrict__ pts,
                            float* __restrict__ cols) {
    int m = blockIdx.x * 256 + threadIdx.x;     // 0..4095
    int k = blockIdx.y;
    int b = blockIdx.z;
    int y = m >> 6, x = m & 63;
    float pty = pts[(b * 18 + 2 * k) * HW + m];
    float ptx = pts[(b * 18 + 2 * k + 1) * HW + m];
    float bx = (float)(k - 4);
    float py = pty + (float)y;
    float px = ((ptx - bx) + (float)x) + bx;
    float y0f = floorf(py), x0f = floorf(px);
    int y0 = (int)y0f, x0 = (int)x0f;
    float wy = py - y0f, wx = px - x0f;
    float w00 = (1.f - wy) * (1.f - wx);
    float w01 = (1.f - wy) * wx;
    float w10 = wy * (1.f - wx);
    float w11 = wy * wx;
    bool vy0 = (y0 >= 0) && (y0 <= 63);
    bool vy1 = (y0 + 1 >= 0) && (y0 + 1 <= 63);
    bool vx0 = (x0 >= 0) && (x0 <= 63);
    bool vx1 = (x0 + 1 >= 0) && (x0 + 1 <= 63);
    w00 = (vy0 && vx0) ? w00 : 0.f;
    w01 = (vy0 && vx1) ? w01 : 0.f;
    w10 = (vy1 && vx0) ? w10 : 0.f;
    w11 = (vy1 && vx1) ? w11 : 0.f;
    int y0c = min(max(y0, 0), 63), y1c = min(max(y0 + 1, 0), 63);
    int x0c = min(max(x0, 0), 63), x1c = min(max(x0 + 1, 0), 63);
    int i00 = y0c * 64 + x0c, i01 = y0c * 64 + x1c;
    int i10 = y1c * 64 + x0c, i11 = y1c * 64 + x1c;
    const float* ib = img + (size_t)b * CC * HW;
    float* cb = cols + ((size_t)b * KK + (size_t)k * CC) * HW + m;
#pragma unroll 4
    for (int c = 0; c < CC; c++) {
        const float* ic = ib + (size_t)c * HW;
        float v = w00 * __ldg(ic + i00) + w01 * __ldg(ic + i01)
                + w10 * __ldg(ic + i10) + w11 * __ldg(ic + i11);
        cb[(size_t)c * HW] = v;
    }
}

// ---------------- GroupNorm stats: one block per (b,g) --------------------
__global__ void gn_stats(const float* __restrict__ raw) {
    int bg = blockIdx.x;
    const float* p = raw + (size_t)bg * CPG * HW;
    float s = 0.f, ss = 0.f;
    for (int i = threadIdx.x; i < CPG * HW; i += 256) {
        float v = p[i];
        s += v; ss += v * v;
    }
    __shared__ float sh[512];
    sh[threadIdx.x] = s;
    sh[256 + threadIdx.x] = ss;
    __syncthreads();
    for (int o = 128; o > 0; o >>= 1) {
        if (threadIdx.x < o) {
            sh[threadIdx.x] += sh[threadIdx.x + o];
            sh[256 + threadIdx.x] += sh[256 + threadIdx.x + o];
        }
        __syncthreads();
    }
    if (threadIdx.x == 0) {
        const float inv_n = 1.f / (float)(CPG * HW);
        float mean = sh[0] * inv_n;
        float var = sh[256] * inv_n - mean * mean;
        g_mu[bg] = mean;
        g_rstd[bg] = rsqrtf(var + 1e-5f);
    }
}

// ---------------- normalize + affine + ReLU -------------------------------
__global__ void gn_apply(const float* __restrict__ raw,
                         const float* __restrict__ gamma,
                         const float* __restrict__ beta,
                         float* __restrict__ out) {
    int i = blockIdx.x * 256 + threadIdx.x;
    int c = (i >> 12) & 255;
    int bg = i >> 15;
    float v = (raw[i] - g_mu[bg]) * g_rstd[bg] * gamma[c] + beta[c];
    out[i] = fmaxf(v, 0.f);
}

// ---------------- TF32 tensor-core GEMM ------------------------------------
// C[b][n][m] = sum_kk A[b][kk][m] * Bw[kk][n]
// M = spatial (rows of mma), N = channels. BM=BN=128, BK=16.
// 128 threads = 4 warps in 2x2, each warp a 64x64 tile (4x8 m16n8k8 frags).
// Shared layout swizzle: addr = k*128 + (col ^ ((k&3)<<3)) -> conflict-free
// for both staging writes and fragment loads.

__device__ __forceinline__ uint32_t f2tf32(float x) {
    uint32_t r;
    asm("cvt.rna.tf32.f32 %0, %1;" : "=r"(r) : "f"(x));
    return r;
}

__device__ __forceinline__ void mma_tf32(float* d, uint32_t a0, uint32_t a1,
                                         uint32_t a2, uint32_t a3,
                                         uint32_t b0, uint32_t b1) {
    asm volatile(
        "mma.sync.aligned.m16n8k8.row.col.f32.tf32.tf32.f32 "
        "{%0,%1,%2,%3}, {%4,%5,%6,%7}, {%8,%9}, {%0,%1,%2,%3};"
        : "+f"(d[0]), "+f"(d[1]), "+f"(d[2]), "+f"(d[3])
        : "r"(a0), "r"(a1), "r"(a2), "r"(a3), "r"(b0), "r"(b1));
}

#define BKT 16

__global__ void __launch_bounds__(128, 2)
tgemm(const float* __restrict__ A,      // [B][KK][HW]
      const float* __restrict__ Bw,     // [KK][ldb]
      float* __restrict__ Cout,
      const float* __restrict__ bias,   // [Nreal] or nullptr
      int Nreal, int ldb, long cBatch) {
    __shared__ uint32_t As[BKT * 128];
    __shared__ uint32_t Bs[BKT * 128];
    int bm = blockIdx.x * 128, bn = blockIdx.y * 128, b = blockIdx.z;
    const float* Ab = A + (size_t)b * KK * HW + bm;
    const float* Bb = Bw + bn;
    int tid = threadIdx.x;
    int warp = tid >> 5, lane = tid & 31;
    int wm = (warp & 1) * 64, wn = (warp >> 1) * 64;
    int r = lane >> 2, c = lane & 3;

    float acc[4][8][4];
#pragma unroll
    for (int mt = 0; mt < 4; mt++)
#pragma unroll
        for (int nt = 0; nt < 8; nt++)
#pragma unroll
            for (int i = 0; i < 4; i++) acc[mt][nt][i] = 0.f;

    for (int k0 = 0; k0 < KK; k0 += BKT) {
        // stage BKTx128 of A and B into swizzled shared (tf32-converted)
#pragma unroll
        for (int s = 0; s < 4; s++) {
            int idx = tid + s * 128;            // 0..511
            int k = idx >> 5;                    // 0..15
            int mq = idx & 31;                   // float4 index
            float4 a4 = *(const float4*)(Ab + (size_t)(k0 + k) * HW + mq * 4);
            float4 b4 = *(const float4*)(Bb + (size_t)(k0 + k) * ldb + mq * 4);
            int col = (mq * 4) ^ ((k & 3) << 3);
            uint32_t* ap = &As[k * 128 + col];
            ap[0] = f2tf32(a4.x); ap[1] = f2tf32(a4.y);
            ap[2] = f2tf32(a4.z); ap[3] = f2tf32(a4.w);
            uint32_t* bp = &Bs[k * 128 + col];
            bp[0] = f2tf32(b4.x); bp[1] = f2tf32(b4.y);
            bp[2] = f2tf32(b4.z); bp[3] = f2tf32(b4.w);
        }
        __syncthreads();
#pragma unroll
        for (int ks = 0; ks < BKT; ks += 8) {
            uint32_t bf[8][2];
#pragma unroll
            for (int nt = 0; nt < 8; nt++) {
                int n0 = wn + nt * 8 + r;
                bf[nt][0] = Bs[(ks + c) * 128 + (n0 ^ (c << 3))];
                bf[nt][1] = Bs[(ks + c + 4) * 128 + (n0 ^ (c << 3))];
            }
#pragma unroll
            for (int mt = 0; mt < 4; mt++) {
                int m0 = wm + mt * 16 + r;
                uint32_t a0 = As[(ks + c) * 128 + (m0 ^ (c << 3))];
                uint32_t a1 = As[(ks + c) * 128 + ((m0 + 8) ^ (c << 3))];
                uint32_t a2 = As[(ks + c + 4) * 128 + (m0 ^ (c << 3))];
                uint32_t a3 = As[(ks + c + 4) * 128 + ((m0 + 8) ^ (c << 3))];
#pragma unroll
                for (int nt = 0; nt < 8; nt++)
                    mma_tf32(acc[mt][nt], a0, a1, a2, a3, bf[nt][0], bf[nt][1]);
            }
        }
        __syncthreads();
    }

    // epilogue: c0:(r,2c) c1:(r,2c+1) c2:(r+8,2c) c3:(r+8,2c+1); rows=m, cols=n
    float* Cb = Cout + (size_t)b * cBatch;
#pragma unroll
    for (int mt = 0; mt < 4; mt++) {
        int m = bm + wm + mt * 16 + r;
#pragma unroll
        for (int nt = 0; nt < 8; nt++) {
            int n = bn + wn + nt * 8 + 2 * c;
            if (n < Nreal) {
                float bv = bias ? bias[n] : 0.f;
                Cb[(size_t)n * HW + m]     = acc[mt][nt][0] + bv;
                Cb[(size_t)n * HW + m + 8] = acc[mt][nt][2] + bv;
            }
            if (n + 1 < Nreal) {
                float bv = bias ? bias[n + 1] : 0.f;
                Cb[(size_t)(n + 1) * HW + m]     = acc[mt][nt][1] + bv;
                Cb[(size_t)(n + 1) * HW + m + 8] = acc[mt][nt][3] + bv;
            }
        }
    }
}

// ---------------- launch ---------------------------------------------------
extern "C" void kernel_launch(void* const* d_in, const int* in_sizes, int n_in,
                              void* d_out, int out_size) {
    const float* cls_feat = (const float*)d_in[0];
    const float* reg_feat = (const float*)d_in[1];
    const float* offc_w   = (const float*)d_in[2];
    const float* offc_b   = (const float*)d_in[3];
    const float* offc_g   = (const float*)d_in[4];
    const float* offc_bt  = (const float*)d_in[5];
    const float* offo_w   = (const float*)d_in[6];
    const float* offo_b   = (const float*)d_in[7];
    const float* clsdc_w  = (const float*)d_in[8];
    const float* cls_g    = (const float*)d_in[9];
    const float* cls_bt   = (const float*)d_in[10];
    const float* regdc_w  = (const float*)d_in[11];
    const float* reg_g    = (const float*)d_in[12];
    const float* reg_bt   = (const float*)d_in[13];

    float* out = (float*)d_out;
    float* pts = out;                         // [4][18][4096]
    float* cls_out = out + (size_t)BB * 18 * HW;
    float* reg_out = cls_out + (size_t)BB * CC * HW;

    float *cols, *t, *raw, *wT1, *wT2, *wTc, *wTr;
    cudaGetSymbolAddress((void**)&cols, g_cols);
    cudaGetSymbolAddress((void**)&t, g_t);
    cudaGetSymbolAddress((void**)&raw, g_raw);
    cudaGetSymbolAddress((void**)&wT1, g_wT1);
    cudaGetSymbolAddress((void**)&wT2, g_wT2);
    cudaGetSymbolAddress((void**)&wTc, g_wTc);
    cudaGetSymbolAddress((void**)&wTr, g_wTr);

    // weight transposes (tiny)
    transpose_w<<<(KK * 256 + 255) / 256, 256>>>(offc_w, wT1, 256, 256);
    transpose_w<<<(KK * 128 + 255) / 256, 256>>>(offo_w, wT2, 18, 128);
    transpose_w<<<(KK * 256 + 255) / 256, 256>>>(clsdc_w, wTc, 256, 256);
    transpose_w<<<(KK * 256 + 255) / 256, 256>>>(regdc_w, wTr, 256, 256);

    const int colsBlocks = (BB * KK * HW) / 256;
    const dim3 gBig(32, 2, 4);   // M=4096/128, N=256/128
    const dim3 gPts(32, 1, 4);   // N=18 (padded 128)
    const dim3 gDef(16, 9, 4);

    // ---- offset branch: conv1 -> GN -> ReLU -> conv2 -> pts ----
    im2col9<<<colsBlocks, 256>>>(reg_feat, cols);
    tgemm<<<gBig, 128>>>(cols, wT1, raw, offc_b, 256, 256, (long)CC * HW);
    gn_stats<<<BB * NG, 256>>>(raw);
    gn_apply<<<(BB * CC * HW) / 256, 256>>>(raw, offc_g, offc_bt, t);
    im2col9<<<colsBlocks, 256>>>(t, cols);
    tgemm<<<gPts, 128>>>(cols, wT2, pts, offo_b, 18, 128, 18L * HW);

    // ---- cls branch: deform conv -> GN -> ReLU ----
    deform_cols<<<gDef, 256>>>(cls_feat, pts, cols);
    tgemm<<<gBig, 128>>>(cols, wTc, raw, nullptr, 256, 256, (long)CC * HW);
    gn_stats<<<BB * NG, 256>>>(raw);
    gn_apply<<<(BB * CC * HW) / 256, 256>>>(raw, cls_g, cls_bt, cls_out);

    // ---- reg branch: deform conv -> GN -> ReLU ----
    deform_cols<<<gDef, 256>>>(reg_feat, pts, cols);
    tgemm<<<gBig, 128>>>(cols, wTr, raw, nullptr, 256, 256, (long)CC * HW);
    gn_stats<<<BB * NG, 256>>>(raw);
    gn_apply<<<(BB * CC * HW) / 256, 256>>>(raw, reg_g, reg_bt, reg_out);
}